// round 9
// baseline (speedup 1.0000x reference)
#include <cuda_runtime.h>
#include <cstdint>

#define TLEN 4096
#define NH 32
#define HS 64
#define DIM (NH*HS)
#define NSLOT 16
#define STRIDE 336   // floats/slot: w64|k64|a64|b64|r64|v16

// grid=128 (32 heads x 4 quarters), block=128 = 4 warps (all 4 SMSPs).
// Warp owns 4 rows; lane owns one row's 8-float j-slice (lane8=j, g=row).
// ONE shared ring per block (16 slots, 14-step lookahead), filled
// cooperatively: 84 x 16B chunks/slot, chunk = tid (tid<84); one
// __syncthreads per PAIR of steps publishes completions block-wide.
//
// Paired sa-recurrence: from S_t compute concurrently
//   sa_t     = dot(S_t, a_t)
//   sa_{t+1} = dot(S_t.*w_t, a_{t+1}) + sa_t*dot(b_t,a_{t+1}) + v_t*dot(k_t,a_{t+1})
// -> one shfl-reduction wave per TWO steps, then two cheap updates.

__device__ __forceinline__ uint32_t smem_u32(const void* p) {
    return (uint32_t)__cvta_generic_to_shared(p);
}

typedef unsigned long long u64;

#define MUL2(d,a,b)   asm("mul.rn.f32x2 %0, %1, %2;"     : "=l"(d) : "l"(a), "l"(b))
#define FMA2(d,a,b,c) asm("fma.rn.f32x2 %0, %1, %2, %3;" : "=l"(d) : "l"(a), "l"(b), "l"(c))
#define PACK2(d,lo,hi)   asm("mov.b64 %0, {%1, %2};" : "=l"(d) : "f"(lo), "f"(hi))
#define UNPACK2(lo,hi,v) asm("mov.b64 {%0, %1}, %2;" : "=f"(lo), "=f"(hi) : "l"(v))

#define DOT8(res, X, Y) do { \
    u64 _p; MUL2(_p, X[0], Y[0]); FMA2(_p, X[1], Y[1], _p); \
    FMA2(_p, X[2], Y[2], _p);     FMA2(_p, X[3], Y[3], _p); \
    float _lo, _hi; UNPACK2(_lo, _hi, _p); res = _lo + _hi; } while(0)

#define RED8(x) do { \
    x += __shfl_xor_sync(0xffffffffu, x, 1); \
    x += __shfl_xor_sync(0xffffffffu, x, 2); \
    x += __shfl_xor_sync(0xffffffffu, x, 4); } while(0)

#define LD4x2(dst, ptr) do { \
    const ulonglong2* _p = (const ulonglong2*)(ptr); \
    ulonglong2 _x0 = _p[0], _x1 = _p[1]; \
    dst[0]=_x0.x; dst[1]=_x0.y; dst[2]=_x1.x; dst[3]=_x1.y; } while(0)

__global__ void __launch_bounds__(128, 1) wkv7_kernel(
    const float* __restrict__ rr, const float* __restrict__ ww,
    const float* __restrict__ kk, const float* __restrict__ vv_,
    const float* __restrict__ aa, const float* __restrict__ bb,
    const float* __restrict__ s0, float* __restrict__ y, float* __restrict__ sout)
{
    const int blk   = blockIdx.x;
    const int h     = blk >> 2;
    const int q     = blk & 3;
    const int tid   = threadIdx.x;
    const int lane  = tid & 31;
    const int lane8 = lane & 7;
    const int g     = lane >> 3;
    const int j0    = lane8 * 8;
    const int hbase = h * HS;
    const int rloc  = (tid >> 5) * 4 + g;  // 0..15
    const int row   = q * 16 + rloc;       // 0..63

    __shared__ __align__(16) float ring[NSLOT][STRIDE];

    u64 S[4];
    LD4x2(S, s0 + ((size_t)h * HS + row) * HS + j0);

    // Cooperative fill: chunk c = tid (c<84), one 16B cp.async per slot.
    // c<80: field f=c>>4 in {w,k,a,b,r}, float offset (c&15)*4.
    // c in 80..83: v (16 floats for this quarter's rows).
    const float* gsrc = 0; uint32_t od = 0;
    {
        int c = tid;
        if (c < 80) {
            int f   = c >> 4;
            int ofs = (c & 15) * 4;
            const float* fp = (f == 0) ? ww : (f == 1) ? kk : (f == 2) ? aa
                            : (f == 3) ? bb : rr;
            gsrc = fp + hbase + ofs;
            od   = f * 64 + ofs;
        } else if (c < 84) {
            gsrc = vv_ + hbase + q * 16 + (c - 80) * 4;
            od   = 320 + (c - 80) * 4;
        }
    }

#define ISSUEP(T0, SA, SB) do { \
    if (gsrc) { \
        asm volatile("cp.async.cg.shared.global [%0], [%1], 16;" \
            :: "r"(smem_u32(&ring[(SA)][0]) + od * 4u), "l"(gsrc + (size_t)(T0) * DIM)); \
        asm volatile("cp.async.cg.shared.global [%0], [%1], 16;" \
            :: "r"(smem_u32(&ring[(SB)][0]) + od * 4u), "l"(gsrc + (size_t)((T0) + 1) * DIM)); \
    } \
    asm volatile("cp.async.commit_group;"); \
} while(0)

    // Prologue: 7 commits covering times/slots 0..13
    #pragma unroll
    for (int n = 0; n < 7; n++) ISSUEP(2 * n, 2 * n, 2 * n + 1);

    asm volatile("cp.async.wait_group 5;");
    __syncthreads();

    u64 a2[4], a3[4];               // a_t, a_{t+1} for the coming pair
    LD4x2(a2, &ring[0][128 + j0]);
    LD4x2(a3, &ring[1][128 + j0]);

    float yv0 = 0.f, yv1 = 0.f;     // deferred y partials (prev pair)
    float* const ybase = y + hbase + row;

// Pair body: steps T (even) and T+1. SA/SB = slots of T,T+1;
// SC/SD = slots of T+2,T+3 (a-prefetch). a2/a3 hold a_T, a_{T+1} on entry.
#define PAIRBODY(T, SA, SB, SC, SD) do { \
    const float* slA = &ring[(SA)][0]; \
    const float* slB = &ring[(SB)][0]; \
    float sa; DOT8(sa, S, a2); \
    u64 wA[4]; LD4x2(wA, slA + j0); \
    u64 sw[4]; \
    MUL2(sw[0], S[0], wA[0]); MUL2(sw[1], S[1], wA[1]); \
    MUL2(sw[2], S[2], wA[2]); MUL2(sw[3], S[3], wA[3]); \
    float Ad; DOT8(Ad, sw, a3); \
    u64 kA[4], bA[4]; \
    LD4x2(kA, slA + 64 + j0); \
    LD4x2(bA, slA + 192 + j0); \
    float Bd; DOT8(Bd, bA, a3); \
    float Cd; DOT8(Cd, kA, a3); \
    RED8(sa); \
    RED8(Ad); \
    RED8(Bd); \
    RED8(Cd); \
    { \
        float u0 = yv0, u1 = yv1; \
        RED8(u0); \
        RED8(u1); \
        int tp = ((T) >= 2) ? (T) - 2 : 0; \
        int tq = ((T) >= 2) ? (T) - 1 : 0; \
        if (lane8 == 0) { \
            ybase[(size_t)tp * DIM] = u0; \
            ybase[(size_t)tq * DIM] = u1; \
        } \
    } \
    u64 rA[4]; LD4x2(rA, slA + 256 + j0); \
    const float vA = slA[320 + rloc]; \
    float sa1 = fmaf(sa, Bd, fmaf(vA, Cd, Ad)); \
    u64 vAb, sab; PACK2(vAb, vA, vA); PACK2(sab, sa, sa); \
    _Pragma("unroll") \
    for (int i = 0; i < 4; i++) { \
        u64 t0; FMA2(t0, vAb, kA[i], sw[i]); \
        FMA2(S[i], sab, bA[i], t0); \
    } \
    { u64 yp; MUL2(yp, S[0], rA[0]); FMA2(yp, S[1], rA[1], yp); \
      FMA2(yp, S[2], rA[2], yp); FMA2(yp, S[3], rA[3], yp); \
      float l, hh; UNPACK2(l, hh, yp); yv0 = l + hh; } \
    u64 wB[4], kB[4], bB[4], rB[4]; \
    LD4x2(wB, slB + j0); \
    LD4x2(kB, slB + 64 + j0); \
    LD4x2(bB, slB + 192 + j0); \
    LD4x2(rB, slB + 256 + j0); \
    const float vB = slB[320 + rloc]; \
    u64 vBb, sa1b; PACK2(vBb, vB, vB); PACK2(sa1b, sa1, sa1); \
    _Pragma("unroll") \
    for (int i = 0; i < 4; i++) { \
        u64 t0; MUL2(t0, S[i], wB[i]); \
        FMA2(t0, vBb, kB[i], t0); \
        FMA2(S[i], sa1b, bB[i], t0); \
    } \
    { u64 yp; MUL2(yp, S[0], rB[0]); FMA2(yp, S[1], rB[1], yp); \
      FMA2(yp, S[2], rB[2], yp); FMA2(yp, S[3], rB[3], yp); \
      float l, hh; UNPACK2(l, hh, yp); yv1 = l + hh; } \
    LD4x2(a2, &ring[(SC)][128 + j0]); \
    LD4x2(a3, &ring[(SD)][128 + j0]); \
} while(0)

    // Main: pairs; slot indices compile-time (tb%16==0).
    for (int tb = 0; tb < TLEN - 16; tb += 16) {
        #pragma unroll
        for (int pu = 0; pu < 8; pu++) {
            const int t = tb + 2 * pu;
            asm volatile("cp.async.wait_group 5;");
            __syncthreads();
            PAIRBODY(t, 2 * pu, 2 * pu + 1, (2 * pu + 2) & 15, (2 * pu + 3) & 15);
            ISSUEP(t + 14, (2 * pu + 14) & 15, (2 * pu + 15) & 15);
        }
    }

    // Tail: issue last pair (4094,4095), drain, then 8 bar-free pairs.
    __syncthreads();
    ISSUEP(TLEN - 2, 14, 15);
    asm volatile("cp.async.wait_group 0;");
    __syncthreads();
    #pragma unroll
    for (int pu = 0; pu < 8; pu++) {
        const int t = TLEN - 16 + 2 * pu;
        PAIRBODY(t, 2 * pu, 2 * pu + 1, (2 * pu + 2) & 15, (2 * pu + 3) & 15);
    }

    // Epilogue: y_{4094}, y_{4095}
    RED8(yv0);
    RED8(yv1);
    if (lane8 == 0) {
        ybase[(size_t)(TLEN - 2) * DIM] = yv0;
        ybase[(size_t)(TLEN - 1) * DIM] = yv1;
    }

    // Final state
    {
        float* sp = sout + ((size_t)h * HS + row) * HS + j0;
        ulonglong2* p = (ulonglong2*)sp;
        ulonglong2 x;
        x.x = S[0]; x.y = S[1]; p[0] = x;
        x.x = S[2]; x.y = S[3]; p[1] = x;
    }
}

extern "C" void kernel_launch(void* const* d_in, const int* in_sizes, int n_in,
                              void* d_out, int out_size) {
    int o = (n_in >= 8) ? 1 : 0;
    const float* r  = (const float*)d_in[o + 0];
    const float* w  = (const float*)d_in[o + 1];
    const float* k  = (const float*)d_in[o + 2];
    const float* v  = (const float*)d_in[o + 3];
    const float* a  = (const float*)d_in[o + 4];
    const float* b  = (const float*)d_in[o + 5];
    const float* s0 = (const float*)d_in[o + 6];

    float* y    = (float*)d_out;                  // x: [T, H, 1, N]
    float* sout = y + (size_t)TLEN * DIM;         // state2_out: [H, N, N]

    wkv7_kernel<<<128, 128>>>(r, w, k, v, a, b, s0, y, sout);
}

// round 10
// speedup vs baseline: 1.1697x; 1.1697x over previous
#include <cuda_runtime.h>
#include <cstdint>

#define TLEN 4096
#define NH 32
#define HS 64
#define DIM (NH*HS)
#define DEPTH 8
#define STRIDE 336   // floats/slot: w64|k64|a64|b64|r64|v8|pad

// grid=128 (32 heads x 4 quarters), block=64 = 2 warps. Warp = 4 groups x 8
// lanes; lane owns TWO rows' j-slices (f32x2-packed). Per-warp cp.async ring
// DEPTH=8, 8x-unrolled (4 pairs) loop with compile-time slots.
//
// PAIRED sa-recurrence (one shfl wave per TWO steps): from S_t,
//   sa_t      = dot(S_t, a_t)                        (per row)
//   sa_{t+1}  = dot(S_t.*w_t, a_{t+1}) + sa_t*dot(b_t,a_{t+1}) + v_t*dot(k_t,a_{t+1})
// All 6 reductions run concurrently; then two cheap state updates.
// y reductions (4/pair) deferred one pair.

__device__ __forceinline__ uint32_t smem_u32(const void* p) {
    return (uint32_t)__cvta_generic_to_shared(p);
}

typedef unsigned long long u64;

#define MUL2(d,a,b)   asm("mul.rn.f32x2 %0, %1, %2;"     : "=l"(d) : "l"(a), "l"(b))
#define FMA2(d,a,b,c) asm("fma.rn.f32x2 %0, %1, %2, %3;" : "=l"(d) : "l"(a), "l"(b), "l"(c))
#define PACK2(d,lo,hi)   asm("mov.b64 %0, {%1, %2};" : "=l"(d) : "f"(lo), "f"(hi))
#define UNPACK2(lo,hi,v) asm("mov.b64 {%0, %1}, %2;" : "=f"(lo), "=f"(hi) : "l"(v))

#define DOT8(res, X, Y) do { \
    u64 _p; MUL2(_p, X[0], Y[0]); FMA2(_p, X[1], Y[1], _p); \
    FMA2(_p, X[2], Y[2], _p);     FMA2(_p, X[3], Y[3], _p); \
    float _lo, _hi; UNPACK2(_lo, _hi, _p); res = _lo + _hi; } while(0)

#define RED8(x) do { \
    x += __shfl_xor_sync(0xffffffffu, x, 1); \
    x += __shfl_xor_sync(0xffffffffu, x, 2); \
    x += __shfl_xor_sync(0xffffffffu, x, 4); } while(0)

#define LD4x2(dst, ptr) do { \
    const ulonglong2* _p = (const ulonglong2*)(ptr); \
    ulonglong2 _x0 = _p[0], _x1 = _p[1]; \
    dst[0]=_x0.x; dst[1]=_x0.y; dst[2]=_x1.x; dst[3]=_x1.y; } while(0)

__global__ void __launch_bounds__(64, 1) wkv7_kernel(
    const float* __restrict__ rr, const float* __restrict__ ww,
    const float* __restrict__ kk, const float* __restrict__ vv_,
    const float* __restrict__ aa, const float* __restrict__ bb,
    const float* __restrict__ s0, float* __restrict__ y, float* __restrict__ sout)
{
    const int blk   = blockIdx.x;
    const int h     = blk >> 2;
    const int q     = blk & 3;
    const int tid   = threadIdx.x;
    const int warp  = tid >> 5;
    const int lane  = tid & 31;
    const int lane8 = lane & 7;
    const int g     = lane >> 3;
    const int j0    = lane8 * 8;
    const int hbase = h * HS;
    const int r0    = q * 16 + warp * 8 + g * 2;   // rows r0, r0+1

    __shared__ __align__(16) float ring[2][DEPTH][STRIDE];

    u64 sA[4], sB[4];
    {
        const float* sp = s0 + ((size_t)h * HS + r0) * HS + j0;
        LD4x2(sA, sp);
        LD4x2(sB, sp + HS);
    }

    // cp.async lane routing (3 x 16B per lane per step)
    const float *g1, *g2, *g3 = 0;
    uint32_t o1, o2, o3 = 0;
    if (lane < 16) { g1 = ww + hbase + lane * 4;        o1 = 0   + lane * 4; }
    else           { g1 = kk + hbase + (lane - 16) * 4; o1 = 64  + (lane - 16) * 4; }
    if (lane < 16) { g2 = aa + hbase + lane * 4;        o2 = 128 + lane * 4; }
    else           { g2 = bb + hbase + (lane - 16) * 4; o2 = 192 + (lane - 16) * 4; }
    if (lane < 16)      { g3 = rr + hbase + lane * 4;                      o3 = 256 + lane * 4; }
    else if (lane < 18) { g3 = vv_ + hbase + q * 16 + warp * 8 + (lane - 16) * 4; o3 = 320 + (lane - 16) * 4; }

#define ISSUE(tt, ss) do { \
    size_t _off = (size_t)(tt) * DIM; \
    uint32_t _sb = smem_u32(&ring[warp][ss][0]); \
    asm volatile("cp.async.cg.shared.global [%0], [%1], 16;" :: "r"(_sb + o1*4u), "l"(g1 + _off)); \
    asm volatile("cp.async.cg.shared.global [%0], [%1], 16;" :: "r"(_sb + o2*4u), "l"(g2 + _off)); \
    if (g3) asm volatile("cp.async.cg.shared.global [%0], [%1], 16;" :: "r"(_sb + o3*4u), "l"(g3 + _off)); \
    asm volatile("cp.async.commit_group;"); \
} while(0)

    #pragma unroll
    for (int i = 0; i < DEPTH; i++) ISSUE(i, i);

    asm volatile("cp.async.wait_group 4;");
    __syncwarp();

    u64 a2[4], a3[4];               // a_t, a_{t+1} for the coming pair
    LD4x2(a2, &ring[warp][0][128 + j0]);
    LD4x2(a3, &ring[warp][1][128 + j0]);

    float yvA0 = 0.f, yvA1 = 0.f, yvB0 = 0.f, yvB1 = 0.f;
    float* const ybase = y + hbase + r0;

// Pair body: steps T (even), T+1. SA/SB slots of T,T+1; SC/SD of T+2,T+3.
// a2/a3 = a_T, a_{T+1} on entry; refreshed to a_{T+2}, a_{T+3} at exit.
#define PAIRBODY(T, SA, SB, SC, SD) do { \
    const float* slA = &ring[warp][SA][0]; \
    const float* slB = &ring[warp][SB][0]; \
    u64 wA[4], kA[4], bA[4], rA[4]; \
    LD4x2(wA, slA + j0); \
    LD4x2(kA, slA + 64 + j0); \
    LD4x2(bA, slA + 192 + j0); \
    LD4x2(rA, slA + 256 + j0); \
    const float2 vA = *(const float2*)(slA + 320 + g * 2); \
    /* dots from S_t: sa_t (2 rows) + lookahead A/B/C */ \
    float sa0, sa1; \
    DOT8(sa0, sA, a2); \
    DOT8(sa1, sB, a2); \
    u64 sw0[4], sw1[4]; \
    MUL2(sw0[0], sA[0], wA[0]); MUL2(sw0[1], sA[1], wA[1]); \
    MUL2(sw0[2], sA[2], wA[2]); MUL2(sw0[3], sA[3], wA[3]); \
    MUL2(sw1[0], sB[0], wA[0]); MUL2(sw1[1], sB[1], wA[1]); \
    MUL2(sw1[2], sB[2], wA[2]); MUL2(sw1[3], sB[3], wA[3]); \
    float Ad0, Ad1, Bd, Cd; \
    DOT8(Ad0, sw0, a3); \
    DOT8(Ad1, sw1, a3); \
    DOT8(Bd, bA, a3); \
    DOT8(Cd, kA, a3); \
    RED8(sa0); \
    RED8(sa1); \
    RED8(Ad0); \
    RED8(Ad1); \
    RED8(Bd); \
    RED8(Cd); \
    /* deferred y of previous pair (independent — fills RED slack) */ \
    { \
        float u0 = yvA0, u1 = yvA1, u2 = yvB0, u3 = yvB1; \
        RED8(u0); \
        RED8(u1); \
        RED8(u2); \
        RED8(u3); \
        int tp = ((T) >= 2) ? (T) - 2 : 0; \
        int tq = ((T) >= 2) ? (T) - 1 : 0; \
        if (lane8 == 0) { \
            *(float2*)&ybase[(size_t)tp * DIM] = make_float2(u0, u1); \
            *(float2*)&ybase[(size_t)tq * DIM] = make_float2(u2, u3); \
        } \
    } \
    /* sa_{t+1} via lookahead */ \
    float sa0n = fmaf(sa0, Bd, fmaf(vA.x, Cd, Ad0)); \
    float sa1n = fmaf(sa1, Bd, fmaf(vA.y, Cd, Ad1)); \
    /* step T update + y partial */ \
    { \
        u64 v0b, v1b, s0b, s1b; \
        PACK2(v0b, vA.x, vA.x); PACK2(v1b, vA.y, vA.y); \
        PACK2(s0b, sa0, sa0);   PACK2(s1b, sa1, sa1); \
        _Pragma("unroll") \
        for (int i = 0; i < 4; i++) { \
            u64 t0; FMA2(t0, v0b, kA[i], sw0[i]); \
            FMA2(sA[i], s0b, bA[i], t0); \
            u64 t1; FMA2(t1, v1b, kA[i], sw1[i]); \
            FMA2(sB[i], s1b, bA[i], t1); \
        } \
        u64 yp0, yp1; \
        MUL2(yp0, sA[0], rA[0]); FMA2(yp0, sA[1], rA[1], yp0); \
        FMA2(yp0, sA[2], rA[2], yp0); FMA2(yp0, sA[3], rA[3], yp0); \
        MUL2(yp1, sB[0], rA[0]); FMA2(yp1, sB[1], rA[1], yp1); \
        FMA2(yp1, sB[2], rA[2], yp1); FMA2(yp1, sB[3], rA[3], yp1); \
        float l0, h0, l1, h1; \
        UNPACK2(l0, h0, yp0); UNPACK2(l1, h1, yp1); \
        yvA0 = l0 + h0; yvA1 = l1 + h1; \
    } \
    /* step T+1 */ \
    { \
        u64 wB[4], kB[4], bB[4], rB[4]; \
        LD4x2(wB, slB + j0); \
        LD4x2(kB, slB + 64 + j0); \
        LD4x2(bB, slB + 192 + j0); \
        LD4x2(rB, slB + 256 + j0); \
        const float2 vB = *(const float2*)(slB + 320 + g * 2); \
        u64 v0b, v1b, s0b, s1b; \
        PACK2(v0b, vB.x, vB.x);  PACK2(v1b, vB.y, vB.y); \
        PACK2(s0b, sa0n, sa0n);  PACK2(s1b, sa1n, sa1n); \
        _Pragma("unroll") \
        for (int i = 0; i < 4; i++) { \
            u64 t0; MUL2(t0, sA[i], wB[i]); \
            FMA2(t0, v0b, kB[i], t0); \
            FMA2(sA[i], s0b, bB[i], t0); \
            u64 t1; MUL2(t1, sB[i], wB[i]); \
            FMA2(t1, v1b, kB[i], t1); \
            FMA2(sB[i], s1b, bB[i], t1); \
        } \
        u64 yp0, yp1; \
        MUL2(yp0, sA[0], rB[0]); FMA2(yp0, sA[1], rB[1], yp0); \
        FMA2(yp0, sA[2], rB[2], yp0); FMA2(yp0, sA[3], rB[3], yp0); \
        MUL2(yp1, sB[0], rB[0]); FMA2(yp1, sB[1], rB[1], yp1); \
        FMA2(yp1, sB[2], rB[2], yp1); FMA2(yp1, sB[3], rB[3], yp1); \
        float l0, h0, l1, h1; \
        UNPACK2(l0, h0, yp0); UNPACK2(l1, h1, yp1); \
        yvB0 = l0 + h0; yvB1 = l1 + h1; \
    } \
    /* a for next pair */ \
    LD4x2(a2, &ring[warp][SC][128 + j0]); \
    LD4x2(a3, &ring[warp][SD][128 + j0]); \
} while(0)

    // Main: 4 pairs per 8x-unrolled block, compile-time slots.
    for (int tb = 0; tb < TLEN - DEPTH; tb += DEPTH) {
        #pragma unroll
        for (int pu = 0; pu < 4; pu++) {
            const int t = tb + 2 * pu;
            asm volatile("cp.async.wait_group 4;");
            __syncwarp();
            PAIRBODY(t, 2 * pu, 2 * pu + 1, (2 * pu + 2) & 7, (2 * pu + 3) & 7);
            ISSUE(t + DEPTH, 2 * pu);
            ISSUE(t + DEPTH + 1, 2 * pu + 1);
        }
    }

    // Tail: everything staged; stale a-prefetch at the very end is unused.
    asm volatile("cp.async.wait_group 0;");
    __syncwarp();
    #pragma unroll
    for (int pu = 0; pu < 4; pu++) {
        const int t = TLEN - DEPTH + 2 * pu;
        PAIRBODY(t, 2 * pu, 2 * pu + 1, (2 * pu + 2) & 7, (2 * pu + 3) & 7);
    }

    // Epilogue: y_{4094}, y_{4095}
    {
        RED8(yvA0);
        RED8(yvA1);
        RED8(yvB0);
        RED8(yvB1);
        if (lane8 == 0) {
            *(float2*)&ybase[(size_t)(TLEN - 2) * DIM] = make_float2(yvA0, yvA1);
            *(float2*)&ybase[(size_t)(TLEN - 1) * DIM] = make_float2(yvB0, yvB1);
        }
    }

    // Final state
    {
        float* sp = sout + ((size_t)h * HS + r0) * HS + j0;
        ulonglong2* p0 = (ulonglong2*)sp;
        ulonglong2* p1 = (ulonglong2*)(sp + HS);
        ulonglong2 x;
        x.x = sA[0]; x.y = sA[1]; p0[0] = x;
        x.x = sA[2]; x.y = sA[3]; p0[1] = x;
        x.x = sB[0]; x.y = sB[1]; p1[0] = x;
        x.x = sB[2]; x.y = sB[3]; p1[1] = x;
    }
}

extern "C" void kernel_launch(void* const* d_in, const int* in_sizes, int n_in,
                              void* d_out, int out_size) {
    int o = (n_in >= 8) ? 1 : 0;
    const float* r  = (const float*)d_in[o + 0];
    const float* w  = (const float*)d_in[o + 1];
    const float* k  = (const float*)d_in[o + 2];
    const float* v  = (const float*)d_in[o + 3];
    const float* a  = (const float*)d_in[o + 4];
    const float* b  = (const float*)d_in[o + 5];
    const float* s0 = (const float*)d_in[o + 6];

    float* y    = (float*)d_out;                  // x: [T, H, 1, N]
    float* sout = y + (size_t)TLEN * DIM;         // state2_out: [H, N, N]

    wkv7_kernel<<<128, 64>>>(r, w, k, v, a, b, s0, y, sout);
}